// round 14
// baseline (speedup 1.0000x reference)
#include <cuda_runtime.h>
#include <cstdint>

#define N_NODES 100000
#define DIM 16
#define NF   (N_NODES * DIM)       // total floats in node matrix
#define N4   (NF / 4)              // float4 count

// Edge-message accumulator (sum of x[src]*prob, WITHOUT the weight factor —
// weight commutes with the segment-sum and is applied in finalize).
// Zero-initialized at module load; finalize re-zeros it every call.
__device__ float4 g_acc[N4];

// ---------------------------------------------------------------------------
// Kernel 1: scatter — measured-best configuration (R7/R13 shape).
// 4 threads per edge (thread = one 16B chunk of the row). Per-block dtype
// detect on the first 64 8-byte words (int32 data read as int64 puts random
// node ids in the high words -> outside [0, N_NODES) almost surely).
// One red.global.add.v4.f32 per thread (no-return 128b L2 reduction) — the
// kernel sits on the REDG per-lane issue floor (~55us for 12.8M lane-ops).
// NEW: griddepcontrol.launch_dependents after the RED — PDL trigger so the
// finalize kernel can launch during this kernel's drain; the trigger's
// visibility contract covers the preceding RED.
// ---------------------------------------------------------------------------
__global__ void __launch_bounds__(256)
ldl_scatter_kernel(const float4* __restrict__ x,
                   const void* __restrict__ eidx,
                   const float* __restrict__ probs,
                   int E) {
    __shared__ int s_ok[2];
    {
        int tid = threadIdx.x;
        if (tid < 64) {
            long long v = ((const long long*)eidx)[tid];
            bool ok = (v >= 0 && v < N_NODES);
            unsigned b = __ballot_sync(0xFFFFFFFFu, ok);
            if ((tid & 31) == 0) s_ok[tid >> 5] = (b == 0xFFFFFFFFu);
        }
        __syncthreads();
    }
    bool is64 = (s_ok[0] && s_ok[1]);

    int t = blockIdx.x * blockDim.x + threadIdx.x;
    int e = t >> 2;
    int c = t & 3;
    if (e < E) {
        long long s, d;
        if (is64) {
            const long long* p = (const long long*)eidx;
            s = __ldg(p + e);
            d = __ldg(p + E + e);
        } else {
            const int* p = (const int*)eidx;
            s = __ldg(p + e);
            d = __ldg(p + E + e);
        }
        if (s >= 0 && s < N_NODES && d >= 0 && d < N_NODES) {  // backstop
            float pr = __ldg(probs + e);
            float4 xv = __ldg(x + s * 4 + c);
            float a0 = xv.x * pr;
            float a1 = xv.y * pr;
            float a2 = xv.z * pr;
            float a3 = xv.w * pr;
            float* op = (float*)g_acc + d * DIM + c * 4;
            asm volatile(
                "red.global.add.v4.f32 [%0], {%1, %2, %3, %4};"
                :: "l"(op), "f"(a0), "f"(a1), "f"(a2), "f"(a3)
                : "memory");
        }
    }
    // PDL trigger: dependents may launch once every CTA has executed this
    // (or exited). Placed after the RED so prior writes are covered by the
    // trigger/wait visibility contract.
    asm volatile("griddepcontrol.launch_dependents;" ::: "memory");
}

// ---------------------------------------------------------------------------
// Kernel 2: finalize — out = clip(x*(1+slw) + acc*weight, 0, 1), re-zero acc.
// 1 float4/thread, 1563 blocks (measured best). PDL: front-load everything
// independent of the scatter result (x, weight, slw, x*s), THEN
// griddepcontrol.wait, THEN read g_acc.
// ---------------------------------------------------------------------------
__global__ void __launch_bounds__(256)
ldl_final_kernel(const float4* __restrict__ x,
                 const float* __restrict__ weight,
                 const float* __restrict__ slw,
                 float4* __restrict__ out) {
    int i = blockIdx.x * blockDim.x + threadIdx.x;

    float s = 0.0f;
    float4 wv = make_float4(0.f, 0.f, 0.f, 0.f);
    float4 xs = make_float4(0.f, 0.f, 0.f, 0.f);
    if (i < N4) {
        s = 1.0f + __ldg(slw);
        wv = __ldg((const float4*)weight + (i & 3));
        float4 xv = x[i];
        xs.x = xv.x * s; xs.y = xv.y * s;
        xs.z = xv.z * s; xs.w = xv.w * s;
    }

    // Wait for the scatter grid's trigger; makes its REDs visible.
    asm volatile("griddepcontrol.wait;" ::: "memory");

    if (i < N4) {
        float4 av = g_acc[i];
        float4 v;
        v.x = fminf(fmaxf(fmaf(av.x, wv.x, xs.x), 0.0f), 1.0f);
        v.y = fminf(fmaxf(fmaf(av.y, wv.y, xs.y), 0.0f), 1.0f);
        v.z = fminf(fmaxf(fmaf(av.z, wv.z, xs.z), 0.0f), 1.0f);
        v.w = fminf(fmaxf(fmaf(av.w, wv.w, xs.w), 0.0f), 1.0f);
        out[i] = v;
        g_acc[i] = make_float4(0.0f, 0.0f, 0.0f, 0.0f);
    }
}

// ---------------------------------------------------------------------------
// Launch. Inputs (metadata order):
//   d_in[0] x                [N_NODES, 16] float32
//   d_in[1] edge_index       [2, E]        int64 OR int32 (runtime-detected)
//   d_in[2] edge_probs       [E]           float32
//   d_in[3] weight           [16]          float32
//   d_in[4] self_loop_weight scalar        float32
// Graph: [scatter ->(programmatic edge) finalize]. The finalize is launched
// with the programmatic-stream-serialization attribute so it may begin
// during the scatter's drain; its g_acc reads sit behind griddepcontrol.wait.
// ---------------------------------------------------------------------------
extern "C" void kernel_launch(void* const* d_in, const int* in_sizes, int n_in,
                              void* d_out, int out_size) {
    const float4* x     = (const float4*)d_in[0];
    const void*   eidx  = d_in[1];
    const float*  probs = (const float*)d_in[2];
    const float*  w     = (const float*)d_in[3];
    const float*  slw   = (const float*)d_in[4];
    float*        out   = (float*)d_out;

    const int E = in_sizes[2];   // edge_probs element count
    const int T = 256;

    long long n = 4LL * E;
    int gScat = (int)((n + T - 1) / T);
    ldl_scatter_kernel<<<gScat, T>>>(x, eidx, probs, E);

    // Finalize with programmatic (PDL) dependency on the scatter.
    cudaLaunchConfig_t cfg = {};
    cfg.gridDim  = dim3((N4 + T - 1) / T, 1, 1);
    cfg.blockDim = dim3(T, 1, 1);
    cfg.dynamicSmemBytes = 0;
    cfg.stream = 0;   // legacy default stream (same as <<<>>> above)
    cudaLaunchAttribute attrs[1];
    attrs[0].id = cudaLaunchAttributeProgrammaticStreamSerialization;
    attrs[0].val.programmaticStreamSerializationAllowed = 1;
    cfg.attrs = attrs;
    cfg.numAttrs = 1;
    cudaLaunchKernelEx(&cfg, ldl_final_kernel, x, w, slw, (float4*)out);
}